// round 3
// baseline (speedup 1.0000x reference)
#include <cuda_runtime.h>
#include <cuda_bf16.h>

#define B_ROWS   16384
#define CWIN     10
#define KNEG     10
#define DIM      128
#define VEC      (DIM / 4)          // 32 float4 per row -> 1 per lane
#define ROWS_PER_BLOCK 8
#define NBLOCKS  (B_ROWS / ROWS_PER_BLOCK)   // 2048
#define EPS      1e-9f

// Scratch for deterministic reduction (no allocations allowed).
__device__ float g_block_partial[NBLOCKS];

__global__ __launch_bounds__(256) void cbow_loss_kernel(
    const int*   __restrict__ ctx,      // [B, CWIN]
    const int*   __restrict__ tgt,      // [B]
    const int*   __restrict__ neg,      // [B, KNEG]
    const float* __restrict__ in_emb,   // [VOCAB, DIM]
    const float* __restrict__ out_emb)  // [VOCAB, DIM]
{
    const int warp = threadIdx.x >> 5;
    const int lane = threadIdx.x & 31;
    const int row  = blockIdx.x * ROWS_PER_BLOCK + warp;

    const float4* __restrict__ in4  = (const float4*)in_emb;
    const float4* __restrict__ out4 = (const float4*)out_emb;

    // ---- context mean (10 independent gathers, high MLP) ----
    float4 acc = make_float4(0.f, 0.f, 0.f, 0.f);
#pragma unroll
    for (int i = 0; i < CWIN; i++) {
        int idx = __ldg(&ctx[row * CWIN + i]);
        float4 v = __ldg(&in4[(size_t)idx * VEC + lane]);
        acc.x += v.x; acc.y += v.y; acc.z += v.z; acc.w += v.w;
    }
    const float inv = 1.0f / (float)CWIN;
    acc.x *= inv; acc.y *= inv; acc.z *= inv; acc.w *= inv;

    // ---- 11 dot-product partial scores (independent gathers) ----
    float s[KNEG + 1];
    {
        int t = __ldg(&tgt[row]);
        float4 v = __ldg(&out4[(size_t)t * VEC + lane]);
        s[0] = acc.x * v.x + acc.y * v.y + acc.z * v.z + acc.w * v.w;
    }
#pragma unroll
    for (int k = 0; k < KNEG; k++) {
        int idx = __ldg(&neg[row * KNEG + k]);
        float4 v = __ldg(&out4[(size_t)idx * VEC + lane]);
        s[1 + k] = acc.x * v.x + acc.y * v.y + acc.z * v.z + acc.w * v.w;
    }

    // ---- warp reductions (butterfly) ----
#pragma unroll
    for (int j = 0; j < KNEG + 1; j++) {
#pragma unroll
        for (int off = 16; off > 0; off >>= 1)
            s[j] += __shfl_xor_sync(0xffffffffu, s[j], off);
    }

    // ---- per-row loss, deterministic block reduction ----
    __shared__ float sh[ROWS_PER_BLOCK];
    if (lane == 0) {
        // pos: log(sigmoid(x) + eps)
        float loss = logf(1.0f / (1.0f + expf(-s[0])) + EPS);
#pragma unroll
        for (int k = 0; k < KNEG; k++) {
            // sigmoid(-x) = 1 / (1 + e^{x})
            loss += logf(1.0f / (1.0f + expf(s[1 + k])) + EPS);
        }
        sh[warp] = loss;
    }
    __syncthreads();
    if (threadIdx.x == 0) {
        float t = 0.f;
#pragma unroll
        for (int w = 0; w < ROWS_PER_BLOCK; w++) t += sh[w];
        g_block_partial[blockIdx.x] = t;
    }
}

__global__ __launch_bounds__(1024) void cbow_reduce_kernel(float* __restrict__ out)
{
    __shared__ float sh[1024];
    float t = 0.f;
    for (int i = threadIdx.x; i < NBLOCKS; i += 1024)
        t += g_block_partial[i];
    sh[threadIdx.x] = t;
    __syncthreads();
#pragma unroll
    for (int off = 512; off > 0; off >>= 1) {
        if (threadIdx.x < off) sh[threadIdx.x] += sh[threadIdx.x + off];
        __syncthreads();
    }
    if (threadIdx.x == 0)
        out[0] = -sh[0] / (float)B_ROWS;
}

extern "C" void kernel_launch(void* const* d_in, const int* in_sizes, int n_in,
                              void* d_out, int out_size)
{
    const int*   ctx     = (const int*)d_in[0];   // context [B, CWIN]
    const int*   tgt     = (const int*)d_in[1];   // target [B]
    const int*   neg     = (const int*)d_in[2];   // negatives [B, KNEG]
    const float* in_emb  = (const float*)d_in[3]; // [VOCAB, DIM]
    const float* out_emb = (const float*)d_in[4]; // [VOCAB, DIM]
    float*       out     = (float*)d_out;

    cbow_loss_kernel<<<NBLOCKS, 256>>>(ctx, tgt, neg, in_emb, out_emb);
    cbow_reduce_kernel<<<1, 1024>>>(out);
}

// round 4
// speedup vs baseline: 1.1778x; 1.1778x over previous
#include <cuda_runtime.h>
#include <cuda_bf16.h>

#define B_ROWS   16384
#define CWIN     10
#define KNEG     10
#define NSCORE   (KNEG + 1)
#define DIM      128
#define VEC      (DIM / 4)          // 32 float4 per row -> 1 per lane
#define ROWS_PER_BLOCK 8
#define NTHREADS 256
#define NBLOCKS  (B_ROWS / ROWS_PER_BLOCK)   // 2048
#define EPS      1e-9f

// Scratch for deterministic reduction (no allocations allowed).
__device__ float        g_block_partial[NBLOCKS];
__device__ unsigned int g_done_counter = 0u;

__global__ __launch_bounds__(NTHREADS) void cbow_loss_kernel(
    const int*   __restrict__ ctx,      // [B, CWIN]
    const int*   __restrict__ tgt,      // [B]
    const int*   __restrict__ neg,      // [B, KNEG]
    const float* __restrict__ in_emb,   // [VOCAB, DIM]
    const float* __restrict__ out_emb,  // [VOCAB, DIM]
    float*       __restrict__ out)
{
    const int warp = threadIdx.x >> 5;
    const int lane = threadIdx.x & 31;
    const int row  = blockIdx.x * ROWS_PER_BLOCK + warp;

    const float4* __restrict__ in4  = (const float4*)in_emb;
    const float4* __restrict__ out4 = (const float4*)out_emb;

    // ---- context mean (10 independent gathers, high MLP) ----
    float4 acc = make_float4(0.f, 0.f, 0.f, 0.f);
#pragma unroll
    for (int i = 0; i < CWIN; i++) {
        int idx = __ldg(&ctx[row * CWIN + i]);
        float4 v = __ldg(&in4[(size_t)idx * VEC + lane]);
        acc.x += v.x; acc.y += v.y; acc.z += v.z; acc.w += v.w;
    }
    const float inv = 1.0f / (float)CWIN;
    acc.x *= inv; acc.y *= inv; acc.z *= inv; acc.w *= inv;

    // ---- 11 dot-product partial scores (independent gathers) ----
    float s[NSCORE];
    {
        int t = __ldg(&tgt[row]);
        float4 v = __ldg(&out4[(size_t)t * VEC + lane]);
        s[0] = acc.x * v.x + acc.y * v.y + acc.z * v.z + acc.w * v.w;
    }
#pragma unroll
    for (int k = 0; k < KNEG; k++) {
        int idx = __ldg(&neg[row * KNEG + k]);
        float4 v = __ldg(&out4[(size_t)idx * VEC + lane]);
        s[1 + k] = acc.x * v.x + acc.y * v.y + acc.z * v.z + acc.w * v.w;
    }

    // ---- warp reductions (butterfly) ----
#pragma unroll
    for (int j = 0; j < NSCORE; j++) {
#pragma unroll
        for (int off = 16; off > 0; off >>= 1)
            s[j] += __shfl_xor_sync(0xffffffffu, s[j], off);
    }

    // ---- per-row loss: spread 11 transcendental terms across lanes 0..10 ----
    // pos term (j==0): log(sigmoid(+s0)+eps) = log(1/(1+e^{-s0}) + eps)
    // neg terms:       log(sigmoid(-sj)+eps) = log(1/(1+e^{+sj}) + eps)
    float term = 0.f;
    if (lane < NSCORE) {
        float x = (lane == 0) ? -s[0] : s[lane];
        term = __logf(__frcp_rn(1.0f + __expf(x)) + EPS);
    }
    // reduce lanes 0..15 (lanes 11..31 contribute 0)
#pragma unroll
    for (int off = 8; off > 0; off >>= 1)
        term += __shfl_xor_sync(0xffffffffu, term, off);
    // lane 0 now holds sum over lanes 0..15? (need lanes 0..10 only; offsets 8,4,2,1
    // fold lanes 0..15 into lane 0, lanes 16..31 separately -> lane 0 has 0..15, ok)

    __shared__ float sh[ROWS_PER_BLOCK];
    if (lane == 0) sh[warp] = term;
    __syncthreads();

    __shared__ bool amLast;
    if (threadIdx.x == 0) {
        float t = 0.f;
#pragma unroll
        for (int w = 0; w < ROWS_PER_BLOCK; w++) t += sh[w];
        g_block_partial[blockIdx.x] = t;
        __threadfence();
        unsigned prev = atomicAdd(&g_done_counter, 1u);
        amLast = (prev == NBLOCKS - 1);
    }
    __syncthreads();

    // ---- last block: deterministic final reduction over fixed index order ----
    if (amLast) {
        float t = 0.f;
        for (int i = threadIdx.x; i < NBLOCKS; i += NTHREADS)
            t += __ldcg(&g_block_partial[i]);           // L2 read, fixed order
#pragma unroll
        for (int off = 16; off > 0; off >>= 1)
            t += __shfl_xor_sync(0xffffffffu, t, off);

        __shared__ float shf[NTHREADS / 32];
        if (lane == 0) shf[warp] = t;
        __syncthreads();
        if (threadIdx.x == 0) {
            float total = 0.f;
#pragma unroll
            for (int w = 0; w < NTHREADS / 32; w++) total += shf[w];
            out[0] = -total / (float)B_ROWS;
            g_done_counter = 0u;   // reset for next graph replay (deterministic)
        }
    }
}

extern "C" void kernel_launch(void* const* d_in, const int* in_sizes, int n_in,
                              void* d_out, int out_size)
{
    const int*   ctx     = (const int*)d_in[0];   // context [B, CWIN]
    const int*   tgt     = (const int*)d_in[1];   // target [B]
    const int*   neg     = (const int*)d_in[2];   // negatives [B, KNEG]
    const float* in_emb  = (const float*)d_in[3]; // [VOCAB, DIM]
    const float* out_emb = (const float*)d_in[4]; // [VOCAB, DIM]
    float*       out     = (float*)d_out;

    cbow_loss_kernel<<<NBLOCKS, NTHREADS>>>(ctx, tgt, neg, in_emb, out_emb, out);
}